// round 1
// baseline (speedup 1.0000x reference)
#include <cuda_runtime.h>
#include <math.h>

#define BATCH    16384
#define MAZE_LEN 3844
#define NIDX     120
#define NQUAD    30   // 120 / 4

// Sorted gather-column table (2 seed indices + 118 chain indices, dup 3721 kept).
__device__ __align__(16) static const int d_idx[NIDX] = {
       1,    6,    9,   13,   17,   21,   25,   29,   33,   37,   41,   45,
      49,   53,   57,   61,   65,   69,   73,   77,   81,   85,   89,   93,
      97,  101,  105,  109,  113,  117,  121,  125,
     245,  249,  369,  373,  493,  497,  617,  621,  741,  745,  865,  869,
     989,  993, 1113, 1117, 1237, 1241, 1361, 1365, 1485, 1489, 1609, 1613,
    1733, 1737, 1857, 1861, 1981, 1985,
    2105, 2109, 2229, 2233, 2353, 2357, 2477, 2481, 2601, 2605, 2725, 2729,
    2849, 2853, 2973, 2977, 3097, 3101, 3221, 3225, 3345, 3349, 3469, 3473,
    3593, 3597, 3717, 3721, 3721, 3725, 3729, 3733,
    3737, 3741, 3745, 3749, 3753, 3757, 3761, 3765, 3769, 3773, 3777, 3781,
    3785, 3789, 3793, 3797, 3801, 3805, 3809, 3813, 3817, 3821, 3825, 3829,
    3839, 3841
};

__device__ __forceinline__ float fast_rcp(float x) {
    float r;
    asm("rcp.approx.ftz.f32 %0, %1;" : "=f"(r) : "f"(x));
    return r;
}

// One warp per row. Lane l (< 30) owns 4 consecutive sorted indices and folds
// their four reciprocals into ONE MUFU.RCP:
//   1/x+1/y+1/z+1/w = ((x+y)*zw + (z+w)*xy) * rcp(xy*zw)
// Row result = min(log(S - 119), 90), S = sum of all 120 reciprocals.
__global__ __launch_bounds__(256)
void fuzzy_chain_kernel(const float* __restrict__ maze, float* __restrict__ out)
{
    const int warp_global = (blockIdx.x * blockDim.x + threadIdx.x) >> 5;
    const int lane        = threadIdx.x & 31;
    const int warp_local  = threadIdx.x >> 5;

    float s = 0.0f;
    if (warp_global < BATCH && lane < NQUAD) {
        const float* __restrict__ row = maze + (size_t)warp_global * MAZE_LEN;
        const int4 q = reinterpret_cast<const int4*>(d_idx)[lane];
        const float x = __ldg(row + q.x);
        const float y = __ldg(row + q.y);
        const float z = __ldg(row + q.z);
        const float w = __ldg(row + q.w);
        const float a   = x * y;
        const float b   = z * w;
        const float num = (x + y) * b + (z + w) * a;
        s = num * fast_rcp(a * b);
    }

    // Warp reduction of S over the 30 active lanes.
    #pragma unroll
    for (int off = 16; off > 0; off >>= 1)
        s += __shfl_xor_sync(0xffffffffu, s, off);

    __shared__ float warp_vals[8];
    if (lane == 0) {
        float v = 0.0f;
        if (warp_global < BATCH) {
            // -log(clip(1/(1+u), exp(-90))) == min(log(S-119), 90).
            // x==0 -> rcp=inf -> log(inf)=inf -> fminf -> 90 (matches clamp).
            // two zeros -> 0*inf=NaN -> fminf(NaN,90)=90 (matches clamp).
            v = fminf(logf(s - 119.0f), 90.0f);
        }
        warp_vals[warp_local] = v;
    }
    __syncthreads();

    if (threadIdx.x == 0) {
        float t = 0.0f;
        #pragma unroll
        for (int i = 0; i < 8; i++) t += warp_vals[i];
        // Pre-scale by exact power-of-two 1/BATCH; one atomic per block (2048 total).
        atomicAdd(out, t * (1.0f / (float)BATCH));
    }
}

extern "C" void kernel_launch(void* const* d_in, const int* in_sizes, int n_in,
                              void* d_out, int out_size)
{
    const float* maze = (const float*)d_in[0];
    float*       out  = (float*)d_out;

    // d_out is poisoned; zero the accumulator (capturable).
    cudaMemsetAsync(out, 0, sizeof(float), 0);

    const int warps_per_block = 8;                       // 256 threads
    const int blocks = BATCH / warps_per_block;          // 2048
    fuzzy_chain_kernel<<<blocks, 256>>>(maze, out);
}

// round 2
// speedup vs baseline: 1.1140x; 1.1140x over previous
#include <cuda_runtime.h>
#include <math.h>

#define BATCH    16384
#define MAZE_LEN 3844          // = 961 float4 per row, rows are 16B-aligned

// Needed columns (120 values, 3721 double-counted):
//  A    : {1, 6} U {4l+1 : l=2..31}                      -> float4 l,  comp .y (.z for lane 1)
//  mid  : {124p+245, 124p+249 : p=0..27}                 -> float4 31p+61 / 31p+62, comp .y
//  tail : {3717+4l : l=0..28} U {3721 dup, 3839, 3841}   -> float4 929+l (29->930, 30->959, 31->960)
// 8 dummy slots (mid lanes 28..31) contribute rcp(1)=1 each -> subtract in constant:
//  -log(clip(prod,e^-90)) == min(log(S_true - 119), 90) == min(log(S - 127), 90)

__device__ __forceinline__ float fast_rcp(float x) {
    float r;
    asm("rcp.approx.ftz.f32 %0, %1;" : "=f"(r) : "f"(x));
    return r;
}

__global__ __launch_bounds__(256)
void fuzzy_chain_kernel(const float* __restrict__ maze, float* __restrict__ out)
{
    const int warp_global = (blockIdx.x * blockDim.x + threadIdx.x) >> 5;
    const int lane        = threadIdx.x & 31;
    const int warp_local  = threadIdx.x >> 5;

    float s = 0.0f;
    if (warp_global < BATCH) {
        const float4* __restrict__ row =
            reinterpret_cast<const float4*>(maze + (size_t)warp_global * MAZE_LEN);

        // ---- per-lane float4 offsets -------------------------------------
        const int a_u = lane;                           // head block
        int t_u = 929 + lane;                           // tail block
        if (lane == 29) t_u = 930;                      // duplicate 3721
        if (lane == 30) t_u = 959;                      // 3839 at .w
        if (lane == 31) t_u = 960;                      // 3841 at .y
        const bool mid_active = (lane < 28);
        const int m_u1 = mid_active ? (31 * lane + 61) : 61;
        const int m_u2 = m_u1 + 1;

        // ---- issue all 4 wide loads up front (MLP=4) ---------------------
        const float4 va = __ldg(row + a_u);
        const float4 vt = __ldg(row + t_u);
        const float4 v1 = __ldg(row + m_u1);
        const float4 v2 = __ldg(row + m_u2);

        // ---- component extraction ----------------------------------------
        const float x = (lane == 1)  ? va.z : va.y;     // 1, 6, 4l+1
        const float y = (lane == 30) ? vt.w : vt.y;     // 3717+4l / 3721 / 3839 / 3841
        const float z = mid_active ? v1.y : 1.0f;       // 124l+245
        const float w = mid_active ? v2.y : 1.0f;       // 124l+249

        // ---- fold 4 reciprocals into one MUFU.RCP ------------------------
        const float a   = x * y;
        const float b   = z * w;
        const float num = (x + y) * b + (z + w) * a;
        s = num * fast_rcp(a * b);
    }

    // Warp reduction of S.
    #pragma unroll
    for (int off = 16; off > 0; off >>= 1)
        s += __shfl_xor_sync(0xffffffffu, s, off);

    __shared__ float warp_vals[8];
    if (lane == 0) {
        float v = 0.0f;
        if (warp_global < BATCH) {
            // S includes 8 dummy 1.0-reciprocals: true arg is (S - 8) - 119.
            // x==0 -> inf -> fminf -> 90; two zeros -> NaN -> fminf -> 90 (matches clip).
            v = fminf(logf(s - 127.0f), 90.0f);
        }
        warp_vals[warp_local] = v;
    }
    __syncthreads();

    if (threadIdx.x == 0) {
        float t = 0.0f;
        #pragma unroll
        for (int i = 0; i < 8; i++) t += warp_vals[i];
        atomicAdd(out, t * (1.0f / (float)BATCH));   // exact power-of-two scale
    }
}

extern "C" void kernel_launch(void* const* d_in, const int* in_sizes, int n_in,
                              void* d_out, int out_size)
{
    const float* maze = (const float*)d_in[0];
    float*       out  = (float*)d_out;

    cudaMemsetAsync(out, 0, sizeof(float), 0);

    const int warps_per_block = 8;                  // 256 threads
    const int blocks = BATCH / warps_per_block;     // 2048
    fuzzy_chain_kernel<<<blocks, 256>>>(maze, out);
}

// round 3
// speedup vs baseline: 1.1944x; 1.0722x over previous
#include <cuda_runtime.h>
#include <math.h>

#define BATCH    16384
#define MAZE_LEN 3844          // = 961 float4 per row, rows 16B-aligned
#define NWARPS   8192          // warps total; each warp does rows w and w+8192

// Needed columns (120 values, 3721 double-counted):
//  A    : {1, 6} U {4l+1 : l=2..31}                      -> float4 l,  comp .y (.z for lane 1)
//  mid  : {124p+245, 124p+249 : p=0..27}                 -> float4 31p+61 / 31p+62, comp .y
//  tail : {3717+4l : l=0..28} U {3721 dup, 3839, 3841}   -> float4 929+l (29->930, 30->959, 31->960)
// 8 dummy slots (mid lanes 28..31) contribute rcp(1)=1 each, absorbed in the constant:
//  -log(clip(prod, e^-90)) == min(log(S - 127), 90)

__device__ __forceinline__ float fast_rcp(float x) {
    float r;
    asm("rcp.approx.ftz.f32 %0, %1;" : "=f"(r) : "f"(x));
    return r;
}

// Per-lane contribution for one row: 4 gathered values folded into ONE MUFU.RCP.
__device__ __forceinline__ float lane_quad(const float4 va, const float4 vt,
                                           const float4 v1, const float4 v2,
                                           int lane, bool mid_active)
{
    const float x = (lane == 1)  ? va.z : va.y;
    const float y = (lane == 30) ? vt.w : vt.y;
    const float z = mid_active ? v1.y : 1.0f;
    const float w = mid_active ? v2.y : 1.0f;
    const float a   = x * y;
    const float b   = z * w;
    const float num = (x + y) * b + (z + w) * a;
    return num * fast_rcp(a * b);
}

__global__ __launch_bounds__(256)
void fuzzy_chain_kernel(const float* __restrict__ maze, float* __restrict__ out)
{
    const int warp_global = (blockIdx.x * blockDim.x + threadIdx.x) >> 5;
    const int lane        = threadIdx.x & 31;
    const int warp_local  = threadIdx.x >> 5;

    // ---- per-lane float4 offsets (shared by both rows) -------------------
    const int a_u = lane;
    int t_u = 929 + lane;
    if (lane == 29) t_u = 930;                      // duplicate 3721
    if (lane == 30) t_u = 959;                      // 3839 at .w
    if (lane == 31) t_u = 960;                      // 3841 at .y
    const bool mid_active = (lane < 28);
    const int m_u1 = mid_active ? (31 * lane + 61) : 61;
    const int m_u2 = m_u1 + 1;

    const float4* __restrict__ row0 =
        reinterpret_cast<const float4*>(maze + (size_t)warp_global * MAZE_LEN);
    const float4* __restrict__ row1 =
        reinterpret_cast<const float4*>(maze + (size_t)(warp_global + NWARPS) * MAZE_LEN);

    // ---- front-batch all 8 wide loads (MLP_p1 = 8) -----------------------
    const float4 va0 = __ldg(row0 + a_u);
    const float4 vt0 = __ldg(row0 + t_u);
    const float4 v10 = __ldg(row0 + m_u1);
    const float4 v20 = __ldg(row0 + m_u2);
    const float4 va1 = __ldg(row1 + a_u);
    const float4 vt1 = __ldg(row1 + t_u);
    const float4 v11 = __ldg(row1 + m_u1);
    const float4 v21 = __ldg(row1 + m_u2);

    float s0 = lane_quad(va0, vt0, v10, v20, lane, mid_active);
    float s1 = lane_quad(va1, vt1, v11, v21, lane, mid_active);

    // ---- warp reduction of both rows' S ----------------------------------
    #pragma unroll
    for (int off = 16; off > 0; off >>= 1) {
        s0 += __shfl_xor_sync(0xffffffffu, s0, off);
        s1 += __shfl_xor_sync(0xffffffffu, s1, off);
    }

    __shared__ float warp_vals[8];
    if (lane == 0) {
        // x==0 -> inf -> fminf -> 90; two zeros -> NaN -> fminf -> 90 (matches clip).
        const float v0 = fminf(logf(s0 - 127.0f), 90.0f);
        const float v1 = fminf(logf(s1 - 127.0f), 90.0f);
        warp_vals[warp_local] = v0 + v1;
    }
    __syncthreads();

    if (threadIdx.x == 0) {
        float t = 0.0f;
        #pragma unroll
        for (int i = 0; i < 8; i++) t += warp_vals[i];
        atomicAdd(out, t * (1.0f / (float)BATCH));   // exact power-of-two scale
    }
}

extern "C" void kernel_launch(void* const* d_in, const int* in_sizes, int n_in,
                              void* d_out, int out_size)
{
    const float* maze = (const float*)d_in[0];
    float*       out  = (float*)d_out;

    cudaMemsetAsync(out, 0, sizeof(float), 0);

    const int blocks = NWARPS / 8;                  // 1024 CTAs, 256 threads each
    fuzzy_chain_kernel<<<blocks, 256>>>(maze, out);
}